// round 1
// baseline (speedup 1.0000x reference)
#include <cuda_runtime.h>
#include <math.h>

// Problem constants
#define TOKENS_M 16384   // B*N = 4*4096
#define CTX_M    4096    // B*M = 4*1024
#define EMB      1024
#define CTXD     768
#define NHEAD    16
#define HDIM     64
#define SEQ_N    4096
#define SEQ_M    1024
#define ATT_SCALE 0.125f  // HEAD_DIM^-0.5

// Scratch (static device globals; no runtime allocation)
__device__ float g_Q[TOKENS_M * EMB];   // 64 MB
__device__ float g_K[CTX_M * EMB];      // 16 MB
__device__ float g_V[CTX_M * EMB];      // 16 MB
__device__ float g_A[TOKENS_M * EMB];   // 64 MB

// ---------------------------------------------------------------------------
// Tiled fp32 GEMM: C[M,N] = A[M,K] @ B[K,N] (+ bias broadcast over rows)
// BM=BN=128, BK=8, 256 threads, 8x8 microtile per thread.
// Requires M%128==0, N%128==0, K%8==0 (all shapes here satisfy this).
// ---------------------------------------------------------------------------
__global__ __launch_bounds__(256) void sgemm128(
    const float* __restrict__ A, const float* __restrict__ B,
    float* __restrict__ C, int M, int N, int K, const float* __restrict__ bias)
{
    __shared__ float As[8][128];
    __shared__ float Bs[8][128];

    const int tid  = threadIdx.x;
    const int bx   = blockIdx.x;          // N / 128
    const int by   = blockIdx.y;          // M / 128
    const int arow = tid >> 1;            // 0..127
    const int acol = (tid & 1) << 2;      // 0 or 4
    const int brow = tid >> 5;            // 0..7
    const int bcol = (tid & 31) << 2;     // 0..124
    const int tx   = tid & 15;
    const int ty   = tid >> 4;

    const float* Ap = A + (size_t)(by * 128 + arow) * K + acol;
    const float* Bp = B + (size_t)brow * N + bx * 128 + bcol;

    float acc[8][8];
#pragma unroll
    for (int i = 0; i < 8; i++)
#pragma unroll
        for (int j = 0; j < 8; j++) acc[i][j] = 0.f;

    for (int k0 = 0; k0 < K; k0 += 8) {
        float4 av = *(const float4*)(Ap + k0);
        As[acol + 0][arow] = av.x;
        As[acol + 1][arow] = av.y;
        As[acol + 2][arow] = av.z;
        As[acol + 3][arow] = av.w;
        *(float4*)&Bs[brow][bcol] = *(const float4*)(Bp + (size_t)k0 * N);
        __syncthreads();

#pragma unroll
        for (int k = 0; k < 8; k++) {
            float a[8], b[8];
            *(float4*)&a[0] = *(const float4*)&As[k][ty * 8];
            *(float4*)&a[4] = *(const float4*)&As[k][ty * 8 + 4];
            *(float4*)&b[0] = *(const float4*)&Bs[k][tx * 8];
            *(float4*)&b[4] = *(const float4*)&Bs[k][tx * 8 + 4];
#pragma unroll
            for (int i = 0; i < 8; i++)
#pragma unroll
                for (int j = 0; j < 8; j++)
                    acc[i][j] = fmaf(a[i], b[j], acc[i][j]);
        }
        __syncthreads();
    }

#pragma unroll
    for (int i = 0; i < 8; i++) {
        const int row = by * 128 + ty * 8 + i;
        float* Cp = C + (size_t)row * N + bx * 128 + tx * 8;
#pragma unroll
        for (int j4 = 0; j4 < 8; j4 += 4) {
            float4 v;
            v.x = acc[i][j4 + 0];
            v.y = acc[i][j4 + 1];
            v.z = acc[i][j4 + 2];
            v.w = acc[i][j4 + 3];
            if (bias) {
                const float* bp = bias + bx * 128 + tx * 8 + j4;
                v.x += bp[0]; v.y += bp[1]; v.z += bp[2]; v.w += bp[3];
            }
            *(float4*)(Cp + j4) = v;
        }
    }
}

// ---------------------------------------------------------------------------
// Fused flash-attention over one (batch, head, 64-query tile).
// grid = (SEQ_N/64, NHEAD, B), block = 256 (16x16), 4x4 microtile.
// Online softmax; K iterated in 64-key tiles.
// ---------------------------------------------------------------------------
#define TSTR 68                                  // padded smem row stride (floats)
#define ATTN_SMEM_BYTES ((3 * 64 * TSTR + 64 * 64) * 4)

__global__ __launch_bounds__(256) void attn_kernel(
    const float* __restrict__ Qg, const float* __restrict__ Kg,
    const float* __restrict__ Vg, float* __restrict__ Og)
{
    extern __shared__ float sm[];
    float (*Qt)[TSTR] = (float(*)[TSTR])sm;                       // Q transposed [d][q]
    float (*Kt)[TSTR] = (float(*)[TSTR])(sm + 64 * TSTR);         // K transposed [d][k]
    float (*Ps)[TSTR] = (float(*)[TSTR])(sm + 2 * 64 * TSTR);     // P transposed [k][q]
    float (*Vs)[64]   = (float(*)[64])  (sm + 3 * 64 * TSTR);     // V [k][dv]

    const int tid    = threadIdx.x;
    const int tx     = tid & 15;
    const int ty     = tid >> 4;
    const int qbase  = blockIdx.z * SEQ_N + blockIdx.x * 64;
    const int kvbase = blockIdx.z * SEQ_M;
    const int hcol   = blockIdx.y * HDIM;

    // Load Q tile transposed
    for (int idx = tid; idx < 64 * 64; idx += 256) {
        const int q = idx >> 6, d = idx & 63;
        Qt[d][q] = Qg[(size_t)(qbase + q) * EMB + hcol + d];
    }

    float m[4], l[4], o[4][4];
#pragma unroll
    for (int i = 0; i < 4; i++) {
        m[i] = -1e30f; l[i] = 0.f;
#pragma unroll
        for (int j = 0; j < 4; j++) o[i][j] = 0.f;
    }

    for (int kt = 0; kt < SEQ_M; kt += 64) {
        __syncthreads();   // protects Kt/Vs/Ps from previous iteration readers
        for (int idx = tid; idx < 64 * 64; idx += 256) {
            const int r = idx >> 6, d = idx & 63;
            const size_t gidx = (size_t)(kvbase + kt + r) * EMB + hcol + d;
            Kt[d][r] = Kg[gidx];
            Vs[r][d] = Vg[gidx];
        }
        __syncthreads();

        // S = Q @ K^T (4x4 microtile, reduce over d=64)
        float s[4][4];
#pragma unroll
        for (int i = 0; i < 4; i++)
#pragma unroll
            for (int j = 0; j < 4; j++) s[i][j] = 0.f;

#pragma unroll 8
        for (int d = 0; d < 64; d++) {
            float a[4], b[4];
            *(float4*)a = *(const float4*)&Qt[d][ty * 4];
            *(float4*)b = *(const float4*)&Kt[d][tx * 4];
#pragma unroll
            for (int i = 0; i < 4; i++)
#pragma unroll
                for (int j = 0; j < 4; j++)
                    s[i][j] = fmaf(a[i], b[j], s[i][j]);
        }

        // Online softmax (rows owned jointly by the 16 tx threads of this ty)
#pragma unroll
        for (int i = 0; i < 4; i++) {
#pragma unroll
            for (int j = 0; j < 4; j++) s[i][j] *= ATT_SCALE;
            float rm = fmaxf(fmaxf(s[i][0], s[i][1]), fmaxf(s[i][2], s[i][3]));
#pragma unroll
            for (int off = 8; off >= 1; off >>= 1)
                rm = fmaxf(rm, __shfl_xor_sync(0xffffffffu, rm, off, 16));
            const float mn   = fmaxf(m[i], rm);
            const float corr = __expf(m[i] - mn);
            m[i] = mn;
            float rs = 0.f;
#pragma unroll
            for (int j = 0; j < 4; j++) {
                const float p = __expf(s[i][j] - mn);
                s[i][j] = p;
                rs += p;
            }
#pragma unroll
            for (int off = 8; off >= 1; off >>= 1)
                rs += __shfl_xor_sync(0xffffffffu, rs, off, 16);
            l[i] = l[i] * corr + rs;
#pragma unroll
            for (int j = 0; j < 4; j++) o[i][j] *= corr;
        }

        // Stage P transposed for the PV GEMM
#pragma unroll
        for (int j = 0; j < 4; j++)
#pragma unroll
            for (int i = 0; i < 4; i++)
                Ps[tx * 4 + j][ty * 4 + i] = s[i][j];
        __syncthreads();

        // O += P @ V (reduce over 64 keys)
#pragma unroll 4
        for (int kk = 0; kk < 64; kk++) {
            float a[4], b[4];
#pragma unroll
            for (int i = 0; i < 4; i++) a[i] = Ps[kk][ty * 4 + i];
            *(float4*)b = *(const float4*)&Vs[kk][tx * 4];
#pragma unroll
            for (int i = 0; i < 4; i++)
#pragma unroll
                for (int j = 0; j < 4; j++)
                    o[i][j] = fmaf(a[i], b[j], o[i][j]);
        }
    }

    // Normalize and write out (layout [b*N + q][h*64 + dv])
#pragma unroll
    for (int i = 0; i < 4; i++) {
        const float inv = 1.f / l[i];
        float4 v;
        v.x = o[i][0] * inv; v.y = o[i][1] * inv;
        v.z = o[i][2] * inv; v.w = o[i][3] * inv;
        *(float4*)&Og[(size_t)(qbase + ty * 4 + i) * EMB + hcol + tx * 4] = v;
    }
}

// ---------------------------------------------------------------------------
// Launch
// ---------------------------------------------------------------------------
extern "C" void kernel_launch(void* const* d_in, const int* in_sizes, int n_in,
                              void* d_out, int out_size)
{
    const float* tokens  = (const float*)d_in[0];
    const float* context = (const float*)d_in[1];
    const float* Wq      = (const float*)d_in[2];
    const float* Wk      = (const float*)d_in[3];
    const float* Wv      = (const float*)d_in[4];
    const float* Wo      = (const float*)d_in[5];
    const float* bo      = (const float*)d_in[6];
    float* out = (float*)d_out;

    float *gQ, *gK, *gV, *gA;
    cudaGetSymbolAddress((void**)&gQ, g_Q);
    cudaGetSymbolAddress((void**)&gK, g_K);
    cudaGetSymbolAddress((void**)&gV, g_V);
    cudaGetSymbolAddress((void**)&gA, g_A);

    cudaFuncSetAttribute(attn_kernel,
                         cudaFuncAttributeMaxDynamicSharedMemorySize,
                         ATTN_SMEM_BYTES);

    // Projections
    sgemm128<<<dim3(EMB / 128, TOKENS_M / 128), 256>>>(tokens, Wq, gQ,
                                                       TOKENS_M, EMB, EMB, nullptr);
    sgemm128<<<dim3(EMB / 128, CTX_M / 128), 256>>>(context, Wk, gK,
                                                    CTX_M, EMB, CTXD, nullptr);
    sgemm128<<<dim3(EMB / 128, CTX_M / 128), 256>>>(context, Wv, gV,
                                                    CTX_M, EMB, CTXD, nullptr);

    // Fused attention
    attn_kernel<<<dim3(SEQ_N / 64, NHEAD, 4), 256, ATTN_SMEM_BYTES>>>(gQ, gK, gV, gA);

    // Output projection + bias
    sgemm128<<<dim3(EMB / 128, TOKENS_M / 128), 256>>>(gA, Wo, out,
                                                       TOKENS_M, EMB, EMB, bo);
}

// round 3
// speedup vs baseline: 2.8894x; 2.8894x over previous
#include <cuda_runtime.h>
#include <math.h>

#define TOKENS_M 16384   // B*N
#define CTX_M    4096    // B*M
#define EMB      1024
#define CTXD     768
#define NHEAD    16
#define HDIM     64
#define SEQ_N    4096
#define SEQ_M    1024
#define ATT_SCALE 0.125f

// Scratch (static device globals)
__device__ float g_Q[TOKENS_M * EMB];
__device__ float g_K[CTX_M * EMB];
__device__ float g_V[CTX_M * EMB];
__device__ float g_A[TOKENS_M * EMB];

__device__ __forceinline__ unsigned f2tf(float x) {
    unsigned r;
    asm("cvt.rna.tf32.f32 %0, %1;" : "=r"(r) : "f"(x));
    return r;
}

__device__ __forceinline__ void mma_tf32(
    float& c0, float& c1, float& c2, float& c3,
    unsigned a0, unsigned a1, unsigned a2, unsigned a3,
    unsigned b0, unsigned b1)
{
    asm volatile(
        "mma.sync.aligned.m16n8k8.row.col.f32.tf32.tf32.f32 "
        "{%0,%1,%2,%3}, {%4,%5,%6,%7}, {%8,%9}, {%0,%1,%2,%3};"
        : "+f"(c0), "+f"(c1), "+f"(c2), "+f"(c3)
        : "r"(a0), "r"(a1), "r"(a2), "r"(a3), "r"(b0), "r"(b1));
}

// ---------------------------------------------------------------------------
// TF32 tensor-core GEMM: C[M,N] = A[M,K] @ B[K,N] (+bias)
// BM=BN=128, BK=32, 256 threads. Warps 2(m)x4(n), warp tile 64x32.
// Requires M%128==0, N%128==0, K%32==0.
// ---------------------------------------------------------------------------
#define ASTR 36   // As row stride (floats): bank = (4*row+col)%32, conflict-free
#define BSTR 136  // Bs row stride

__global__ __launch_bounds__(256) void gemm_tf32(
    const float* __restrict__ A, const float* __restrict__ B,
    float* __restrict__ C, int M, int N, int K, const float* __restrict__ bias)
{
    __shared__ unsigned As[128 * ASTR];
    __shared__ unsigned Bs[32 * BSTR];

    const int tid  = threadIdx.x;
    const int lane = tid & 31;
    const int wid  = tid >> 5;
    const int wm   = (wid >> 2) * 64;   // warp row offset
    const int wn   = (wid & 3) * 32;    // warp col offset
    const int bx   = blockIdx.x * 128;
    const int by   = blockIdx.y * 128;

    float acc[4][4][4];
#pragma unroll
    for (int mt = 0; mt < 4; mt++)
#pragma unroll
        for (int nt = 0; nt < 4; nt++)
#pragma unroll
            for (int c = 0; c < 4; c++) acc[mt][nt][c] = 0.f;

    for (int k0 = 0; k0 < K; k0 += 32) {
        // Stage A tile (128x32), convert to tf32
#pragma unroll
        for (int i = 0; i < 4; i++) {
            const int idx = tid + 256 * i;
            const int r = idx >> 3, c = (idx & 7) * 4;
            float4 v = *(const float4*)(A + (size_t)(by + r) * K + k0 + c);
            unsigned* p = &As[r * ASTR + c];
            p[0] = f2tf(v.x); p[1] = f2tf(v.y); p[2] = f2tf(v.z); p[3] = f2tf(v.w);
        }
        // Stage B tile (32x128)
#pragma unroll
        for (int i = 0; i < 4; i++) {
            const int idx = tid + 256 * i;
            const int r = idx >> 5, c = (idx & 31) * 4;
            float4 v = *(const float4*)(B + (size_t)(k0 + r) * N + bx + c);
            uint4 t;
            t.x = f2tf(v.x); t.y = f2tf(v.y); t.z = f2tf(v.z); t.w = f2tf(v.w);
            *(uint4*)&Bs[r * BSTR + c] = t;
        }
        __syncthreads();

#pragma unroll
        for (int ks = 0; ks < 4; ks++) {
            unsigned a[4][4], b[4][2];
#pragma unroll
            for (int mt = 0; mt < 4; mt++) {
                const int r = wm + mt * 16 + (lane >> 2);
                const int c = ks * 8 + (lane & 3);
                a[mt][0] = As[r * ASTR + c];
                a[mt][1] = As[(r + 8) * ASTR + c];
                a[mt][2] = As[r * ASTR + c + 4];
                a[mt][3] = As[(r + 8) * ASTR + c + 4];
            }
#pragma unroll
            for (int nt = 0; nt < 4; nt++) {
                const int c = wn + nt * 8 + (lane >> 2);
                const int r = ks * 8 + (lane & 3);
                b[nt][0] = Bs[r * BSTR + c];
                b[nt][1] = Bs[(r + 4) * BSTR + c];
            }
#pragma unroll
            for (int mt = 0; mt < 4; mt++)
#pragma unroll
                for (int nt = 0; nt < 4; nt++)
                    mma_tf32(acc[mt][nt][0], acc[mt][nt][1],
                             acc[mt][nt][2], acc[mt][nt][3],
                             a[mt][0], a[mt][1], a[mt][2], a[mt][3],
                             b[nt][0], b[nt][1]);
        }
        __syncthreads();
    }

    // Epilogue
#pragma unroll
    for (int mt = 0; mt < 4; mt++) {
        const int r0 = by + wm + mt * 16 + (lane >> 2);
#pragma unroll
        for (int nt = 0; nt < 4; nt++) {
            const int col = bx + wn + nt * 8 + 2 * (lane & 3);
            float bv0 = 0.f, bv1 = 0.f;
            if (bias) { bv0 = bias[col]; bv1 = bias[col + 1]; }
            float2 v0 = { acc[mt][nt][0] + bv0, acc[mt][nt][1] + bv1 };
            float2 v1 = { acc[mt][nt][2] + bv0, acc[mt][nt][3] + bv1 };
            *(float2*)(C + (size_t)r0 * N + col) = v0;
            *(float2*)(C + (size_t)(r0 + 8) * N + col) = v1;
        }
    }
}

// ---------------------------------------------------------------------------
// TF32 tensor-core flash attention.
// grid = (SEQ_N/128, NHEAD, B), block = 256 (8 warps, 16 q-rows each).
// K iterated in 64-key tiles; online softmax on mma C-fragments.
// ---------------------------------------------------------------------------
#define QSTR 68   // padded row stride (words): bank = (4*row+col)%32
#define ATTN_SMEM ((128 * QSTR + 64 * QSTR + 64 * QSTR + 128 * QSTR) * 4)

__global__ __launch_bounds__(256) void attn_tc(
    const float* __restrict__ Qg, const float* __restrict__ Kg,
    const float* __restrict__ Vg, float* __restrict__ Og)
{
    extern __shared__ unsigned sm[];
    unsigned* Qs = sm;                         // [128][QSTR]  Q (q x d), tf32
    unsigned* Ks = Qs + 128 * QSTR;            // [64][QSTR]   K (key x d), tf32
    unsigned* Vs = Ks + 64 * QSTR;             // [64][QSTR]   V (key x dv), tf32
    unsigned* Ps = Vs + 64 * QSTR;             // [128][QSTR]  P (q x key), tf32

    const int tid    = threadIdx.x;
    const int lane   = tid & 31;
    const int wid    = tid >> 5;
    const int qbase  = blockIdx.z * SEQ_N + blockIdx.x * 128;
    const int kvbase = blockIdx.z * SEQ_M;
    const int hcol   = blockIdx.y * HDIM;

    // Load Q tile (128 x 64) -> tf32 smem
#pragma unroll
    for (int i = 0; i < 8; i++) {
        const int idx = tid + 256 * i;
        const int r = idx >> 4, c = (idx & 15) * 4;
        float4 v = *(const float4*)(Qg + (size_t)(qbase + r) * EMB + hcol + c);
        uint4 t;
        t.x = f2tf(v.x); t.y = f2tf(v.y); t.z = f2tf(v.z); t.w = f2tf(v.w);
        *(uint4*)&Qs[r * QSTR + c] = t;
    }

    // Softmax state: rows r0 = lane>>2, r1 = r0+8 within warp's 16-row stripe
    float m0 = -1e30f, m1 = -1e30f, l0 = 0.f, l1 = 0.f;
    float oacc[8][4];
#pragma unroll
    for (int nt = 0; nt < 8; nt++)
#pragma unroll
        for (int c = 0; c < 4; c++) oacc[nt][c] = 0.f;

    const int qrow = wid * 16 + (lane >> 2);   // local q row (first of pair)

    for (int kt = 0; kt < SEQ_M; kt += 64) {
        __syncthreads();  // all warps done with previous Ks/Vs
        // Stage K and V tiles (64 x 64 each)
#pragma unroll
        for (int i = 0; i < 4; i++) {
            const int idx = tid + 256 * i;
            const int r = idx >> 4, c = (idx & 15) * 4;
            const size_t g = (size_t)(kvbase + kt + r) * EMB + hcol + c;
            float4 kv = *(const float4*)(Kg + g);
            float4 vv = *(const float4*)(Vg + g);
            uint4 tk, tv;
            tk.x = f2tf(kv.x); tk.y = f2tf(kv.y); tk.z = f2tf(kv.z); tk.w = f2tf(kv.w);
            tv.x = f2tf(vv.x); tv.y = f2tf(vv.y); tv.z = f2tf(vv.z); tv.w = f2tf(vv.w);
            *(uint4*)&Ks[r * QSTR + c] = tk;
            *(uint4*)&Vs[r * QSTR + c] = tv;
        }
        __syncthreads();

        // S = Q @ K^T : m=16 (warp stripe), n=64 keys, k=64 d
        float sacc[8][4];
#pragma unroll
        for (int nt = 0; nt < 8; nt++)
#pragma unroll
            for (int c = 0; c < 4; c++) sacc[nt][c] = 0.f;

#pragma unroll
        for (int ks = 0; ks < 8; ks++) {
            unsigned a0, a1, a2, a3;
            {
                const int r = qrow, c = ks * 8 + (lane & 3);
                a0 = Qs[r * QSTR + c];
                a1 = Qs[(r + 8) * QSTR + c];
                a2 = Qs[r * QSTR + c + 4];
                a3 = Qs[(r + 8) * QSTR + c + 4];
            }
#pragma unroll
            for (int nt = 0; nt < 8; nt++) {
                const int key = nt * 8 + (lane >> 2);
                const int d = ks * 8 + (lane & 3);
                unsigned b0 = Ks[key * QSTR + d];
                unsigned b1 = Ks[key * QSTR + d + 4];
                mma_tf32(sacc[nt][0], sacc[nt][1], sacc[nt][2], sacc[nt][3],
                         a0, a1, a2, a3, b0, b1);
            }
        }

        // Online softmax. Thread holds: row r0: sacc[nt][0..1], row r1: sacc[nt][2..3]
        float vmax0 = -1e30f, vmax1 = -1e30f;
#pragma unroll
        for (int nt = 0; nt < 8; nt++) {
#pragma unroll
            for (int c = 0; c < 4; c++) sacc[nt][c] *= ATT_SCALE;
            vmax0 = fmaxf(vmax0, fmaxf(sacc[nt][0], sacc[nt][1]));
            vmax1 = fmaxf(vmax1, fmaxf(sacc[nt][2], sacc[nt][3]));
        }
        vmax0 = fmaxf(vmax0, __shfl_xor_sync(0xffffffffu, vmax0, 1));
        vmax0 = fmaxf(vmax0, __shfl_xor_sync(0xffffffffu, vmax0, 2));
        vmax1 = fmaxf(vmax1, __shfl_xor_sync(0xffffffffu, vmax1, 1));
        vmax1 = fmaxf(vmax1, __shfl_xor_sync(0xffffffffu, vmax1, 2));

        const float mn0 = fmaxf(m0, vmax0);
        const float mn1 = fmaxf(m1, vmax1);
        const float corr0 = __expf(m0 - mn0);
        const float corr1 = __expf(m1 - mn1);
        m0 = mn0; m1 = mn1;

        float rs0 = 0.f, rs1 = 0.f;
#pragma unroll
        for (int nt = 0; nt < 8; nt++) {
            sacc[nt][0] = __expf(sacc[nt][0] - mn0);
            sacc[nt][1] = __expf(sacc[nt][1] - mn0);
            sacc[nt][2] = __expf(sacc[nt][2] - mn1);
            sacc[nt][3] = __expf(sacc[nt][3] - mn1);
            rs0 += sacc[nt][0] + sacc[nt][1];
            rs1 += sacc[nt][2] + sacc[nt][3];
        }
        rs0 += __shfl_xor_sync(0xffffffffu, rs0, 1);
        rs0 += __shfl_xor_sync(0xffffffffu, rs0, 2);
        rs1 += __shfl_xor_sync(0xffffffffu, rs1, 1);
        rs1 += __shfl_xor_sync(0xffffffffu, rs1, 2);
        l0 = l0 * corr0 + rs0;
        l1 = l1 * corr1 + rs1;

        // Rescale O, stage P (per-warp-private rows of Ps)
#pragma unroll
        for (int nt = 0; nt < 8; nt++) {
            oacc[nt][0] *= corr0; oacc[nt][1] *= corr0;
            oacc[nt][2] *= corr1; oacc[nt][3] *= corr1;
            const int col = nt * 8 + 2 * (lane & 3);
            const int rr0 = wid * 16 + (lane >> 2);
            Ps[rr0 * QSTR + col]           = f2tf(sacc[nt][0]);
            Ps[rr0 * QSTR + col + 1]       = f2tf(sacc[nt][1]);
            Ps[(rr0 + 8) * QSTR + col]     = f2tf(sacc[nt][2]);
            Ps[(rr0 + 8) * QSTR + col + 1] = f2tf(sacc[nt][3]);
        }
        __syncwarp();

        // O += P @ V : m=16, n=64 dv, k=64 keys
#pragma unroll
        for (int ks = 0; ks < 8; ks++) {
            unsigned a0, a1, a2, a3;
            {
                const int r = qrow, c = ks * 8 + (lane & 3);
                a0 = Ps[r * QSTR + c];
                a1 = Ps[(r + 8) * QSTR + c];
                a2 = Ps[r * QSTR + c + 4];
                a3 = Ps[(r + 8) * QSTR + c + 4];
            }
#pragma unroll
            for (int nt = 0; nt < 8; nt++) {
                const int key = ks * 8 + (lane & 3);
                const int dv = nt * 8 + (lane >> 2);
                unsigned b0 = Vs[key * QSTR + dv];
                unsigned b1 = Vs[(key + 4) * QSTR + dv];
                mma_tf32(oacc[nt][0], oacc[nt][1], oacc[nt][2], oacc[nt][3],
                         a0, a1, a2, a3, b0, b1);
            }
        }
    }

    // Normalize and write out
    const float inv0 = 1.f / l0;
    const float inv1 = 1.f / l1;
    const int tok0 = qbase + wid * 16 + (lane >> 2);
#pragma unroll
    for (int nt = 0; nt < 8; nt++) {
        const int col = hcol + nt * 8 + 2 * (lane & 3);
        float2 v0 = { oacc[nt][0] * inv0, oacc[nt][1] * inv0 };
        float2 v1 = { oacc[nt][2] * inv1, oacc[nt][3] * inv1 };
        *(float2*)(Og + (size_t)tok0 * EMB + col) = v0;
        *(float2*)(Og + (size_t)(tok0 + 8) * EMB + col) = v1;
    }
}

// ---------------------------------------------------------------------------
extern "C" void kernel_launch(void* const* d_in, const int* in_sizes, int n_in,
                              void* d_out, int out_size)
{
    const float* tokens  = (const float*)d_in[0];
    const float* context = (const float*)d_in[1];
    const float* Wq      = (const float*)d_in[2];
    const float* Wk      = (const float*)d_in[3];
    const float* Wv      = (const float*)d_in[4];
    const float* Wo      = (const float*)d_in[5];
    const float* bo      = (const float*)d_in[6];
    float* out = (float*)d_out;

    float *gQ, *gK, *gV, *gA;
    cudaGetSymbolAddress((void**)&gQ, g_Q);
    cudaGetSymbolAddress((void**)&gK, g_K);
    cudaGetSymbolAddress((void**)&gV, g_V);
    cudaGetSymbolAddress((void**)&gA, g_A);

    cudaFuncSetAttribute(attn_tc,
                         cudaFuncAttributeMaxDynamicSharedMemorySize,
                         ATTN_SMEM);

    // Projections (TF32 tensor cores)
    gemm_tf32<<<dim3(EMB / 128, TOKENS_M / 128), 256>>>(tokens, Wq, gQ,
                                                        TOKENS_M, EMB, EMB, nullptr);
    gemm_tf32<<<dim3(EMB / 128, CTX_M / 128), 256>>>(context, Wk, gK,
                                                     CTX_M, EMB, CTXD, nullptr);
    gemm_tf32<<<dim3(EMB / 128, CTX_M / 128), 256>>>(context, Wv, gV,
                                                     CTX_M, EMB, CTXD, nullptr);

    // Fused attention (TF32 tensor cores)
    attn_tc<<<dim3(SEQ_N / 128, NHEAD, 4), 256, ATTN_SMEM>>>(gQ, gK, gV, gA);

    // Output projection + bias
    gemm_tf32<<<dim3(EMB / 128, TOKENS_M / 128), 256>>>(gA, Wo, out,
                                                        TOKENS_M, EMB, EMB, bo);
}